// round 11
// baseline (speedup 1.0000x reference)
#include <cuda_runtime.h>
#include <stdint.h>

#define NB 256
#define LL 1024
#define TT 128
#define THREADS 128
#define FULL 0xffffffffu

// smem layout (bytes), all 16B-aligned
#define OFF_TRANS 0          // 128*128*4 = 65536 (row-major)
#define OFF_BP    65536      // 1024*128 = 131072 -> 196608
#define OFF_TAGS  196608     // 4096 -> 200704
#define OFF_SURV  200704     // 2*128*8 = 2048 -> 202752
#define OFF_RED   202752     // 1024 -> 203776
#define SMEM_BYTES 203776

__device__ int d_sched[NB];

// order-preserving float <-> uint map
__device__ __forceinline__ unsigned fmap(float f) {
    unsigned u = __float_as_uint(f);
    return (u & 0x80000000u) ? ~u : (u | 0x80000000u);
}
__device__ __forceinline__ float funmap(unsigned u) {
    return __uint_as_float((u & 0x80000000u) ? (u ^ 0x80000000u) : ~u);
}

__device__ __forceinline__ void upd(float &bv, int &bi, float sc, int i) {
    // first-argmax: strictly better, or equal with smaller index (order-independent)
    bool better = (sc > bv) || ((sc == bv) && (i < bi));
    bv = better ? sc : bv;
    bi = better ? i : bi;
}

// ---- pre-kernel: LPT schedule (bitonic sort, descending by length) ----
__global__ void sched_kernel(const int* __restrict__ lengths)
{
    __shared__ unsigned key[NB];
    int i = threadIdx.x;
    unsigned l = (unsigned)max(0, min(LL, lengths[i]));
    key[i] = (l << 8) | (255u - (unsigned)i);      // desc len, asc idx on ties
    __syncthreads();
    for (int k = 2; k <= NB; k <<= 1) {
        for (int j = k >> 1; j > 0; j >>= 1) {
            int ixj = i ^ j;
            if (ixj > i) {
                unsigned a = key[i], b2 = key[ixj];
                bool up = ((i & k) == 0);
                bool sw = up ? (a < b2) : (a > b2);
                if (sw) { key[i] = b2; key[ixj] = a; }
            }
            __syncthreads();
        }
    }
    d_sched[i] = 255 - (int)(key[i] & 0xFFu);
}

__global__ __launch_bounds__(THREADS, 1)
void crf_decode_kernel(const float* __restrict__ x,
                       const int* __restrict__ lengths,
                       const float* __restrict__ trans,
                       float* __restrict__ out)
{
    extern __shared__ char smem[];
    float*   s_trans = (float*)(smem + OFF_TRANS);     // row-major [i][j]
    uint8_t* s_bp    = (uint8_t*)(smem + OFF_BP);
    int*     s_tags  = (int*)(smem + OFF_TAGS);
    int2*    s_surv  = (int2*)(smem + OFF_SURV);       // [2][128] (valbits, src idx)
    float*   s_red   = (float*)(smem + OFF_RED);       // minmax staging

    const int tid = threadIdx.x;
    const int b   = d_sched[blockIdx.x];

    int len = lengths[b];
    if (len > LL) len = LL;
    if (len < 1)  len = 1;

    // ---- cooperative trans load (row-major) + min/max fold ----
    {
        float mx = -3.4e38f, mn = 3.4e38f;
        const float4* t4  = (const float4*)trans;
        float4*       st4 = (float4*)s_trans;
        #pragma unroll 8
        for (int k = tid; k < (TT * TT / 4); k += THREADS) {
            float4 v = t4[k];
            st4[k] = v;
            mx = fmaxf(mx, fmaxf(fmaxf(v.x, v.y), fmaxf(v.z, v.w)));
            mn = fminf(mn, fminf(fminf(v.x, v.y), fminf(v.z, v.w)));
        }
        s_red[tid]       = mx;
        s_red[128 + tid] = mn;
    }
    __syncthreads();

    // ================= forward recurrence: warp 0, warp-synchronous =================
    if (tid < 32) {
        const int lane = tid;

        // fold staged min/max (each lane 4 entries, then redux)
        float mx = -3.4e38f, mn = 3.4e38f;
        #pragma unroll
        for (int c = 0; c < 4; ++c) {
            mx = fmaxf(mx, s_red[lane * 4 + c]);
            mn = fminf(mn, s_red[128 + lane * 4 + c]);
        }
        mx = funmap(__reduce_max_sync(FULL, fmap(mx)));
        mn = -funmap(__reduce_max_sync(FULL, fmap(-mn)));
        float D = (mx - mn) * 1.001f + 0.01f;            // exact-pruning width + margin
        if (!(D >= 0.01f && D <= 1000.0f)) D = 3.0e38f;  // dense fallback if anomalous

        const float* xrow = x + (size_t)b * (LL * TT);

        // state i = 4*lane + c
        float4 xc = ((const float4*)xrow)[lane];
        float s0 = xc.x, s1 = xc.y, s2 = xc.z, s3 = xc.w;

        float4 xp0 = make_float4(0,0,0,0), xp1 = xp0, xp2 = xp0;
        if (len > 1) xp0 = ((const float4*)(xrow + (size_t)1 * TT))[lane];
        if (len > 2) xp1 = ((const float4*)(xrow + (size_t)2 * TT))[lane];
        if (len > 3) xp2 = ((const float4*)(xrow + (size_t)3 * TT))[lane];

        const float* tb = s_trans + (lane << 2);         // this lane's 4 target columns
        const unsigned below = (1u << lane) - 1u;

        // ---- publish survivors of current state into buffer `buf`; returns K ----
        #define PUBLISH(BUF, KOUT)                                                  \
        {                                                                           \
            float lm = fmaxf(fmaxf(s0, s1), fmaxf(s2, s3));                         \
            lm = funmap(__reduce_max_sync(FULL, fmap(lm)));                         \
            float thr = lm - D;                                                     \
            unsigned m0 = __ballot_sync(FULL, s0 >= thr);                           \
            unsigned m1 = __ballot_sync(FULL, s1 >= thr);                           \
            unsigned m2 = __ballot_sync(FULL, s2 >= thr);                           \
            unsigned m3 = __ballot_sync(FULL, s3 >= thr);                           \
            if ((m0 | m1 | m2 | m3) == 0u) { m0 = m1 = m2 = m3 = FULL; }            \
            int p0   = __popc(m0);                                                  \
            int p01  = p0  + __popc(m1);                                            \
            int p012 = p01 + __popc(m2);                                            \
            int2* Lst = s_surv + ((BUF) << 7);                                      \
            if ((m0 >> lane) & 1)                                                   \
                Lst[__popc(m0 & below)]        = make_int2(__float_as_int(s0), (lane<<2)+0); \
            if ((m1 >> lane) & 1)                                                   \
                Lst[p0  + __popc(m1 & below)]  = make_int2(__float_as_int(s1), (lane<<2)+1); \
            if ((m2 >> lane) & 1)                                                   \
                Lst[p01 + __popc(m2 & below)]  = make_int2(__float_as_int(s2), (lane<<2)+2); \
            if ((m3 >> lane) & 1)                                                   \
                Lst[p012+ __popc(m3 & below)]  = make_int2(__float_as_int(s3), (lane<<2)+3); \
            (KOUT) = p012 + __popc(m3);                                             \
        }

        int K;
        PUBLISH(0, K)

        for (int t = 1; t < len; ++t) {
            __syncwarp(FULL);                            // STS(prev publish) -> LDS order

            float4 xt = xp0;
            xp0 = xp1; xp1 = xp2;
            if (t + 3 < len) xp2 = ((const float4*)(xrow + (size_t)(t + 3) * TT))[lane];

            const int2* Lst = s_surv + (((t - 1) & 1) << 7);
            float bv0 = -3.4e38f, bv1 = -3.4e38f, bv2 = -3.4e38f, bv3 = -3.4e38f;
            int   bi0 = 0, bi1 = 0, bi2 = 0, bi3 = 0;

            for (int k = 0; k < K; ++k) {                // K uniform -> converged
                int2 e = Lst[k];                         // broadcast LDS.64
                float sv = __int_as_float(e.x);
                float4 tr = *(const float4*)(tb + (e.y << 7));   // conflict-free LDS.128
                upd(bv0, bi0, sv + tr.x, e.y);
                upd(bv1, bi1, sv + tr.y, e.y);
                upd(bv2, bi2, sv + tr.z, e.y);
                upd(bv3, bi3, sv + tr.w, e.y);
            }

            s0 = bv0 + xt.x;
            s1 = bv1 + xt.y;
            s2 = bv2 + xt.z;
            s3 = bv3 + xt.w;

            unsigned bpw = (unsigned)bi0 | ((unsigned)bi1 << 8) |
                           ((unsigned)bi2 << 16) | ((unsigned)bi3 << 24);
            ((unsigned*)s_bp)[(t << 5) + lane] = bpw;

            PUBLISH(t & 1, K)
        }
        #undef PUBLISH

        // ---- final argmax (first-max index) ----
        float fm = fmaxf(fmaxf(s0, s1), fmaxf(s2, s3));
        fm = funmap(__reduce_max_sync(FULL, fmap(fm)));
        int c0 = (s0 == fm) ? ((lane << 2) + 0) : 0x7fffffff;
        int c1 = (s1 == fm) ? ((lane << 2) + 1) : 0x7fffffff;
        int c2 = (s2 == fm) ? ((lane << 2) + 2) : 0x7fffffff;
        int c3 = (s3 == fm) ? ((lane << 2) + 3) : 0x7fffffff;
        int cand = min(min(c0, c1), min(c2, c3));
        cand = (int)__reduce_min_sync(FULL, (unsigned)cand);
        if (cand > TT - 1) cand = 0;                     // safety, unreachable

        // ---- backward walk: lane 0, smem pointer chase ----
        if (lane == 0) {
            int carry = cand;
            for (int t = len - 1; t >= 1; --t) {
                s_tags[t] = carry;
                carry = (int)s_bp[(t << 7) + carry];
            }
            s_tags[0] = carry;
        }
    }
    __syncthreads();

    // ---- output: float32 tags for t < len, zeros beyond ----
    float* orow = out + b * LL;
    #pragma unroll 2
    for (int k = tid; k < LL / 4; k += THREADS) {
        int base = k << 2;
        float4 v;
        v.x = (base + 0 < len) ? (float)s_tags[base + 0] : 0.0f;
        v.y = (base + 1 < len) ? (float)s_tags[base + 1] : 0.0f;
        v.z = (base + 2 < len) ? (float)s_tags[base + 2] : 0.0f;
        v.w = (base + 3 < len) ? (float)s_tags[base + 3] : 0.0f;
        ((float4*)orow)[k] = v;
    }
}

extern "C" void kernel_launch(void* const* d_in, const int* in_sizes, int n_in,
                              void* d_out, int out_size)
{
    const float* x       = nullptr;
    const int*   lengths = nullptr;
    const float* trans   = nullptr;
    for (int i = 0; i < n_in; ++i) {
        long s = in_sizes[i];
        if      (s == 33554432L || s == 134217728L) x       = (const float*)d_in[i];
        else if (s == 256L      || s == 1024L)      lengths = (const int*)d_in[i];
        else if (s == 16384L    || s == 65536L)     trans   = (const float*)d_in[i];
    }
    if (!x       && n_in > 0) x       = (const float*)d_in[0];
    if (!lengths && n_in > 1) lengths = (const int*)d_in[1];
    if (!trans   && n_in > 3) trans   = (const float*)d_in[3];

    sched_kernel<<<1, NB>>>(lengths);

    cudaFuncSetAttribute(crf_decode_kernel,
                         cudaFuncAttributeMaxDynamicSharedMemorySize, SMEM_BYTES);
    crf_decode_kernel<<<NB, THREADS, SMEM_BYTES>>>(x, lengths, trans, (float*)d_out);
}

// round 12
// speedup vs baseline: 1.3969x; 1.3969x over previous
#include <cuda_runtime.h>
#include <stdint.h>

#define NB 256
#define LL 1024
#define TT 128
#define THREADS 128
#define TSTRIDE 129
#define FULL 0xffffffffu

// smem layout (bytes), all 16B-aligned
#define OFF_TRANST 0          // 128*129*4 = 66048
#define OFF_BP     66048      // 131072 -> 197120
#define OFF_TAGS   197120     // 4096   -> 201216
#define OFF_WMAX   201216     // 2*4*4 = 32 -> 201248
#define OFF_CNT    201248     // 32 -> 201280
#define OFF_SEG    201280     // 2*4*32*8 = 2048 -> 203328
#define OFF_RED    203328     // 1024 -> 204352
#define SMEM_BYTES 204352

__device__ int d_sched[NB];

// order-preserving float <-> uint map
__device__ __forceinline__ unsigned fmap(float f) {
    unsigned u = __float_as_uint(f);
    return (u & 0x80000000u) ? ~u : (u | 0x80000000u);
}
__device__ __forceinline__ float funmap(unsigned u) {
    return __uint_as_float((u & 0x80000000u) ? (u ^ 0x80000000u) : ~u);
}

__device__ __forceinline__ void upd(float &bv, int &bi, float sc, int i) {
    // first-argmax: strictly better, or equal with smaller index (order-independent)
    bool better = (sc > bv) || ((sc == bv) && (i < bi));
    bv = better ? sc : bv;
    bi = better ? i : bi;
}

// ---- pre-kernel: LPT schedule (bitonic sort, descending by length) ----
__global__ void sched_kernel(const int* __restrict__ lengths)
{
    __shared__ unsigned key[NB];
    int i = threadIdx.x;
    unsigned l = (unsigned)max(0, min(LL, lengths[i]));
    key[i] = (l << 8) | (255u - (unsigned)i);      // desc len, asc idx on ties
    __syncthreads();
    for (int k = 2; k <= NB; k <<= 1) {
        for (int j = k >> 1; j > 0; j >>= 1) {
            int ixj = i ^ j;
            if (ixj > i) {
                unsigned a = key[i], b2 = key[ixj];
                bool up = ((i & k) == 0);
                bool sw = up ? (a < b2) : (a > b2);
                if (sw) { key[i] = b2; key[ixj] = a; }
            }
            __syncthreads();
        }
    }
    d_sched[i] = 255 - (int)(key[i] & 0xFFu);
}

__global__ __launch_bounds__(THREADS, 1)
void crf_decode_kernel(const float* __restrict__ x,
                       const int* __restrict__ lengths,
                       const float* __restrict__ trans,
                       float* __restrict__ out)
{
    extern __shared__ char smem[];
    float*    s_transT = (float*)(smem + OFF_TRANST);   // [j][i] stride 129, conflict-free
    uint8_t*  s_bp     = (uint8_t*)(smem + OFF_BP);
    int*      s_tags   = (int*)(smem + OFF_TAGS);
    unsigned* s_wmax   = (unsigned*)(smem + OFF_WMAX);  // [2][4] warp maxima (mapped)
    int*      s_cnt    = (int*)(smem + OFF_CNT);        // [2][4] per-warp counts
    int2*     s_seg    = (int2*)(smem + OFF_SEG);       // [2][4][32] (valbits, idx)
    float*    s_red    = (float*)(smem + OFF_RED);      // staging / final state

    const int tid  = threadIdx.x;
    const int lane = tid & 31;
    const int w    = tid >> 5;
    const int b    = d_sched[blockIdx.x];

    int len = lengths[b];
    if (len > LL) len = LL;
    if (len < 1)  len = 1;

    // ---- transposed trans load + min/max fold ----
    {
        float mx = -3.4e38f, mn = 3.4e38f;
        #pragma unroll 4
        for (int i = 0; i < TT; ++i) {
            float v = trans[i * TT + tid];              // coalesced
            s_transT[tid * TSTRIDE + i] = v;            // conflict-free store
            mx = fmaxf(mx, v);
            mn = fminf(mn, v);
        }
        s_red[tid]       = mx;
        s_red[128 + tid] = mn;
    }
    __syncthreads();

    // all threads fold staged min/max identically -> identical D
    float D;
    {
        float gmx = -3.4e38f, gmn = 3.4e38f;
        const float4* r4 = (const float4*)s_red;        // 16B-aligned broadcast reads
        #pragma unroll 8
        for (int k = 0; k < 32; ++k) {
            float4 a = r4[k];
            gmx = fmaxf(gmx, fmaxf(fmaxf(a.x, a.y), fmaxf(a.z, a.w)));
            float4 c = r4[32 + k];
            gmn = fminf(gmn, fminf(fminf(c.x, c.y), fminf(c.z, c.w)));
        }
        D = (gmx - gmn) * 1.001f + 0.01f;               // exact-pruning width + fp margin
        if (!(D >= 0.01f && D <= 1000.0f)) D = 3.0e38f; // dense fallback if anomalous
    }

    const float* xb = x + (size_t)b * (LL * TT);
    float sj = xb[tid];                                 // state_0[j]

    // depth-3 x prefetch (guarded)
    float xA = (len > 1) ? xb[(size_t)1 * TT + tid] : 0.0f;
    float xB = (len > 2) ? xb[(size_t)2 * TT + tid] : 0.0f;
    float xC = (len > 3) ? xb[(size_t)3 * TT + tid] : 0.0f;

    const float* rowT = s_transT + tid * TSTRIDE;
    const unsigned below = (1u << lane) - 1u;

    // publish current state's per-warp candidates into parity buffer BUF.
    // per-warp threshold => superset of exact set; never empty (warp max passes).
    #define PUBLISH(BUF)                                                        \
    {                                                                           \
        unsigned wmu = __reduce_max_sync(FULL, fmap(sj));                       \
        float wmf = funmap(wmu);                                                \
        bool pred = (sj >= wmf - D);                                            \
        unsigned bal = __ballot_sync(FULL, pred);                               \
        int pos = __popc(bal & below);                                          \
        if (pred)                                                               \
            s_seg[((BUF) << 7) + (w << 5) + pos] = make_int2(__float_as_int(sj), tid); \
        if (lane == 0) {                                                        \
            s_cnt[((BUF) << 2) + w]  = __popc(bal);                             \
            s_wmax[((BUF) << 2) + w] = wmu;                                     \
        }                                                                       \
    }

    PUBLISH(0)

    for (int t = 1; t < len; ++t) {
        __syncthreads();                                // single barrier per step
        const int p  = (t - 1) & 1;
        const int np = t & 1;

        const int4  cn = *(const int4*)(s_cnt + (p << 2));
        const uint4 wm = *(const uint4*)(s_wmax + (p << 2));
        unsigned gm = max(max(wm.x, wm.y), max(wm.z, wm.w));
        float thr = funmap(gm) - D;                     // exact global threshold

        float xcur = xA; xA = xB; xB = xC;
        xC = (t + 3 < len) ? xb[(size_t)(t + 3) * TT + tid] : 0.0f;

        float best = -3.4e38f;
        int   bi   = 0;
        const int2* seg = s_seg + (p << 7);
        #define SCAN(CNT, W2)                                              \
        { const int2* e2 = seg + ((W2) << 5);                              \
          for (int k = 0; k < (CNT); ++k) {                                \
              int2 e = e2[k];                          /* broadcast LDS */ \
              float sv = __int_as_float(e.x);                              \
              if (sv >= thr) {                         /* uniform branch */\
                  float v = sv + rowT[e.y];                                \
                  upd(best, bi, v, e.y);                                   \
              }                                                            \
          } }
        SCAN(cn.x, 0)
        SCAN(cn.y, 1)
        SCAN(cn.z, 2)
        SCAN(cn.w, 3)
        #undef SCAN

        s_bp[(t << 7) + tid] = (uint8_t)bi;
        sj = best + xcur;                               // reference op order

        PUBLISH(np)                                     // writes buffer np (race-free)
    }
    #undef PUBLISH

    // ---- final argmax (first-max) + backward walk ----
    __syncthreads();                                    // protect s_red reuse + bp drain
    s_red[tid] = sj;
    __syncthreads();
    if (tid == 0) {
        float bestf = s_red[0];
        int cand = 0;
        for (int i = 1; i < TT; ++i) {
            float v = s_red[i];
            if (v > bestf) { bestf = v; cand = i; }
        }
        int carry = cand;
        for (int t = len - 1; t >= 1; --t) {
            s_tags[t] = carry;
            carry = (int)s_bp[(t << 7) + carry];
        }
        s_tags[0] = carry;
    }
    __syncthreads();

    // ---- output: float32 tags for t < len, zeros beyond ----
    float* orow = out + b * LL;
    #pragma unroll 2
    for (int k = tid; k < LL / 4; k += THREADS) {
        int base = k << 2;
        float4 v;
        v.x = (base + 0 < len) ? (float)s_tags[base + 0] : 0.0f;
        v.y = (base + 1 < len) ? (float)s_tags[base + 1] : 0.0f;
        v.z = (base + 2 < len) ? (float)s_tags[base + 2] : 0.0f;
        v.w = (base + 3 < len) ? (float)s_tags[base + 3] : 0.0f;
        ((float4*)orow)[k] = v;
    }
}

extern "C" void kernel_launch(void* const* d_in, const int* in_sizes, int n_in,
                              void* d_out, int out_size)
{
    const float* x       = nullptr;
    const int*   lengths = nullptr;
    const float* trans   = nullptr;
    for (int i = 0; i < n_in; ++i) {
        long s = in_sizes[i];
        if      (s == 33554432L || s == 134217728L) x       = (const float*)d_in[i];
        else if (s == 256L      || s == 1024L)      lengths = (const int*)d_in[i];
        else if (s == 16384L    || s == 65536L)     trans   = (const float*)d_in[i];
    }
    if (!x       && n_in > 0) x       = (const float*)d_in[0];
    if (!lengths && n_in > 1) lengths = (const int*)d_in[1];
    if (!trans   && n_in > 3) trans   = (const float*)d_in[3];

    sched_kernel<<<1, NB>>>(lengths);

    cudaFuncSetAttribute(crf_decode_kernel,
                         cudaFuncAttributeMaxDynamicSharedMemorySize, SMEM_BYTES);
    crf_decode_kernel<<<NB, THREADS, SMEM_BYTES>>>(x, lengths, trans, (float*)d_out);
}